// round 2
// baseline (speedup 1.0000x reference)
#include <cuda_runtime.h>
#include <cuda_bf16.h>

// NeighborListForTraining: all intra-molecule ordered pairs (i!=j) for
// 2000 molecules x 64 atoms. Output (float32, concatenated flat):
//   [0,P)    i_idx      (as float)
//   [P,2P)   j_idx      (as float)
//   [2P,3P)  d_ij       (0 where d > cutoff)
//   [3P,6P)  r_ij[P][3] (0 where d > cutoff)
// with P = n_mols * 64*63 = 8,064,000.
//
// Pure HBM-write-bound streamer: one block per molecule, positions staged in
// SMEM, 4 consecutive pairs per thread so every store is an aligned float4.
// Streaming stores (.cs) — output has zero reuse.

#define NPM   64
#define PPM   (NPM * (NPM - 1))    // 4032 pairs per molecule
#define GPM   (PPM / 4)            // 1008 groups of 4 pairs
#define CUTOFF 5.0f
#define BLOCK 256

__device__ __forceinline__ void stcs4(float* p, float4 v) {
    __stcs((float4*)p, v);
}

__global__ __launch_bounds__(BLOCK) void neighborlist_kernel(
    const float* __restrict__ pos,   // [n_atoms, 3]
    float* __restrict__ out,
    int n_mols)
{
    __shared__ float s_pos[NPM * 3];

    const int mol = blockIdx.x;
    const float* mp = pos + (size_t)mol * (NPM * 3);

    // Stage this molecule's 64 positions (192 floats, coalesced).
    for (int k = threadIdx.x; k < NPM * 3; k += BLOCK)
        s_pos[k] = mp[k];
    __syncthreads();

    const long long P = (long long)n_mols * PPM;
    float* __restrict__ out_i = out;
    float* __restrict__ out_j = out + P;
    float* __restrict__ out_d = out + 2 * P;
    float* __restrict__ out_r = out + 3 * P;

    const int atom_base = mol * NPM;
    const long long mol_pair_base = (long long)mol * PPM;

    for (int g = threadIdx.x; g < GPM; g += BLOCK) {
        const int pbase = g * 4;   // local pair index of first pair in group

        float4 fi, fj, fd;
        float  rr[12];
        float* fip = (float*)&fi;
        float* fjp = (float*)&fj;
        float* fdp = (float*)&fd;

        #pragma unroll
        for (int k = 0; k < 4; k++) {
            const int t  = pbase + k;          // 0..4031
            const int il = t / 63;             // i_loc
            const int rm = t - il * 63;
            const int jl = rm + (rm >= il);    // j_loc, skipping i

            const float pix = s_pos[3 * il + 0];
            const float piy = s_pos[3 * il + 1];
            const float piz = s_pos[3 * il + 2];
            const float pjx = s_pos[3 * jl + 0];
            const float pjy = s_pos[3 * jl + 1];
            const float pjz = s_pos[3 * jl + 2];

            float dx = pjx - pix;
            float dy = pjy - piy;
            float dz = pjz - piz;
            float d  = sqrtf(dx * dx + dy * dy + dz * dz);

            const bool in_cut = (d <= CUTOFF);
            if (!in_cut) { d = 0.0f; dx = 0.0f; dy = 0.0f; dz = 0.0f; }

            fip[k] = (float)(atom_base + il);
            fjp[k] = (float)(atom_base + jl);
            fdp[k] = d;
            rr[3 * k + 0] = dx;
            rr[3 * k + 1] = dy;
            rr[3 * k + 2] = dz;
        }

        const long long p = mol_pair_base + pbase;   // p % 4 == 0
        stcs4(out_i + p, fi);
        stcs4(out_j + p, fj);
        stcs4(out_d + p, fd);

        float* orr = out_r + 3 * p;                  // 3p % 4 == 0
        stcs4(orr + 0, *(float4*)(rr + 0));
        stcs4(orr + 4, *(float4*)(rr + 4));
        stcs4(orr + 8, *(float4*)(rr + 8));
    }
}

extern "C" void kernel_launch(void* const* d_in, const int* in_sizes, int n_in,
                              void* d_out, int out_size)
{
    const float* positions = (const float*)d_in[0];
    // in_sizes[0] = n_atoms * 3
    const int n_atoms = in_sizes[0] / 3;
    const int n_mols  = n_atoms / NPM;

    float* out = (float*)d_out;
    neighborlist_kernel<<<n_mols, BLOCK>>>(positions, out, n_mols);
}